// round 5
// baseline (speedup 1.0000x reference)
#include <cuda_runtime.h>
#include <math.h>

#define NB 2
#define LL 1024
#define SS 1024
#define HH 8
#define EE 64
#define KK 6

// Scratch (static device globals: allocation-free rule)
__device__ __align__(16) float g_ht[(size_t)KK*NB*HH*LL*EE];   // htilde[c][n][h][l][e]
__device__ float g_hsq[(size_t)KK*NB*HH*LL];     // ||htilde||^2
__device__ float g_pi[(size_t)NB*HH*LL*KK];      // mixture weights [n][h][l][c]
__device__ __align__(16) float g_keyT[(size_t)NB*HH*EE*SS];    // key transposed [n][h][e][s]
__device__ __align__(16) float g_ksq[(size_t)NB*HH*SS];        // ||key||^2 [n][h][s]

// ---------------------------------------------------------------------------
// Kernel 1: pi = softmax_k(q.M), htilde[c] = tanh(q.C[c]), hsq
// grid (16 l-tiles, H, N*K); thread owns 16 CONSECUTIVE f -> LDS.128 GEMM
// ---------------------------------------------------------------------------
__global__ __launch_bounds__(256) void precompute_kernel(
    const float* __restrict__ q, const float* __restrict__ M,
    const float* __restrict__ C)
{
  int lt = blockIdx.x, h = blockIdx.y;
  int c  = blockIdx.z >> 1;      // z = c*NB + n
  int n  = blockIdx.z & 1;
  int l0 = lt * 64;
  int tid = threadIdx.x;
  __shared__ float sq[64][65];
  __shared__ float sc[64][64];
  __shared__ float sz[64][KK];
  __shared__ float spart[64][4];

  for (int idx = tid; idx < 4096; idx += 256) {
    int l = idx >> 6, e = idx & 63;
    sq[l][e] = q[((size_t)((n*LL + l0 + l)*HH + h))*EE + e];
  }
  for (int idx = tid; idx < 4096; idx += 256)
    sc[idx >> 6][idx & 63] = C[(size_t)(c*HH + h)*4096 + idx];
  __syncthreads();

  if (c == 0) {  // pi computed once (by the c==0 blocks)
    for (int t = tid; t < 64*KK; t += 256) {
      int l = t / KK, k = t % KK;
      float a = 0.f;
      for (int e = 0; e < EE; e++) a += sq[l][e] * M[(h*EE + e)*KK + k];
      sz[l][k] = a;
    }
    __syncthreads();
    if (tid < 64) {
      float mx = sz[tid][0];
      #pragma unroll
      for (int k = 1; k < KK; k++) mx = fmaxf(mx, sz[tid][k]);
      float s = 0.f, ev[KK];
      #pragma unroll
      for (int k = 0; k < KK; k++) { ev[k] = __expf(sz[tid][k] - mx); s += ev[k]; }
      float inv = 1.f / s;
      #pragma unroll
      for (int k = 0; k < KK; k++)
        g_pi[((size_t)((n*HH + h)*LL) + l0 + tid)*KK + k] = ev[k]*inv;
    }
  }

  int lq = tid >> 2;            // row 0..63
  int f0 = (tid & 3) * 16;      // 16 consecutive f per thread
  float a[16];
  #pragma unroll
  for (int j = 0; j < 16; j++) a[j] = 0.f;
  for (int e = 0; e < EE; e++) {
    float qv = sq[lq][e];
    const float4* crow = (const float4*)&sc[e][f0];
    #pragma unroll
    for (int v = 0; v < 4; v++) {
      float4 cv = crow[v];
      a[v*4+0] += qv * cv.x;
      a[v*4+1] += qv * cv.y;
      a[v*4+2] += qv * cv.z;
      a[v*4+3] += qv * cv.w;
    }
  }
  float ssq = 0.f;
  float t[16];
  #pragma unroll
  for (int j = 0; j < 16; j++) {
    t[j] = tanhf(a[j]);
    ssq += t[j]*t[j];
  }
  size_t htbase = ((size_t)((c*NB + n)*HH + h)*LL + l0 + lq)*EE + f0;
  float4* hdst = (float4*)&g_ht[htbase];
  #pragma unroll
  for (int v = 0; v < 4; v++)
    hdst[v] = make_float4(t[v*4], t[v*4+1], t[v*4+2], t[v*4+3]);
  spart[lq][tid & 3] = ssq;
  __syncthreads();
  if (tid < 64)
    g_hsq[(size_t)((c*NB + n)*HH + h)*LL + l0 + tid] =
      spart[tid][0] + spart[tid][1] + spart[tid][2] + spart[tid][3];
}

// ---------------------------------------------------------------------------
// Kernel 2: key transpose -> g_keyT[n][h][e][s], and ksq
// ---------------------------------------------------------------------------
__global__ __launch_bounds__(256) void keyprep_kernel(const float* __restrict__ key)
{
  int st = blockIdx.x, h = blockIdx.y, n = blockIdx.z;
  int s0 = st * 64;
  int tid = threadIdx.x;
  __shared__ float sk[64][65];
  for (int idx = tid; idx < 4096; idx += 256) {
    int s = idx >> 6, e = idx & 63;
    sk[s][e] = key[((size_t)((n*SS + s0 + s)*HH + h))*EE + e];
  }
  __syncthreads();
  for (int idx = tid; idx < 4096; idx += 256) {
    int e = idx >> 6, s = idx & 63;
    g_keyT[((size_t)((n*HH + h)*EE) + e)*SS + s0 + s] = sk[s][e];
  }
  if (tid < 64) {
    float a = 0.f;
    #pragma unroll
    for (int e = 0; e < EE; e++) a += sk[tid][e] * sk[tid][e];
    g_ksq[(size_t)(n*HH + h)*SS + s0 + tid] = a;
  }
}

// ---------------------------------------------------------------------------
// Kernel 3: fused logits + softmax + mixture, codes in PAIRS
// grid (L/16, H, N), 512 threads. Thread tile: 4 l x 8 s (two float4 groups
// at s=4*si and s=512+4*si) x 2 codes. outacc in registers.
// smem: 64KB key double-buffer + 64KB mask(+keylen) tile + ht/ksq/misc.
// ---------------------------------------------------------------------------
#define TLm 16
#define ECm 8

// smem float offsets
#define SMO_KEY   0          // 2 * 8192
#define SMO_MASK  16384      // 16384
#define SMO_HT    32768      // 2048
#define SMO_KSQ   34816      // 1024
#define SMO_HSQ   35840      // 32
#define SMO_PI    35872      // 32
#define SMO_REDM  35904      // 64
#define SMO_REDZ  35968      // 64
#define SMEM_FLOATS 36032
#define SMEM_BYTES (SMEM_FLOATS*4)

__device__ __forceinline__ float kfun(int c, float d, float ns) {
  if (c == 0) return d;                                   // 'L'
  if (c == 1) return -__logf(1.f + ns);                   // 'O' (ns>=0)
  if (c == 2) return -ns;                                 // 'P'
  if (c == 3) { float t = d + 1.f; return t * t; }        // 'Y'
  if (c == 4) return __expf(-0.5f * ns);                  // 'R'
  return __cosf(ns) * __expf(-ns);                        // 'W'
}

__global__ __launch_bounds__(512) void attn_kernel(
    const float* __restrict__ mask, const float* __restrict__ keylen,
    float* __restrict__ out)
{
  extern __shared__ float sm[];
  float* s_key  = sm + SMO_KEY;
  float* s_mask = sm + SMO_MASK;
  float* s_ht2  = sm + SMO_HT;
  float* s_ksq  = sm + SMO_KSQ;
  float* s_hsq2 = sm + SMO_HSQ;
  float* s_pi2  = sm + SMO_PI;
  float* s_redm = sm + SMO_REDM;
  float* s_redz = sm + SMO_REDZ;

  int lt = blockIdx.x, h = blockIdx.y, n = blockIdx.z;
  int l0 = lt * TLm;
  int tid  = threadIdx.x;
  int lg   = tid >> 7;        // 0..3 -> rows lg*4 .. lg*4+3
  int si   = tid & 127;       // s = 4*si+r  and  512+4*si+r
  int lane = tid & 31;
  int w4   = si >> 5;

  for (int s = tid; s < SS; s += 512)
    s_ksq[s] = g_ksq[(size_t)(n*HH + h)*SS + s];

  // mask tile + keylen folded, once per block (reused by all 6 codes)
  {
    const float4* msrc = (const float4*)(mask + ((size_t)n*LL + l0)*SS);
    const float4* klsrc = (const float4*)(keylen + (size_t)n*SS);
    float4* mdst = (float4*)s_mask;
    for (int idx = tid; idx < TLm*SS/4; idx += 512) {
      float4 mv = msrc[idx];
      float4 kv = klsrc[idx & 255];
      mdst[idx] = make_float4(mv.x+kv.x, mv.y+kv.y, mv.z+kv.z, mv.w+kv.w);
    }
  }

  float outacc[4][8];
  #pragma unroll
  for (int i = 0; i < 4; i++)
    #pragma unroll
    for (int j = 0; j < 8; j++) outacc[i][j] = 0.f;

  const float4* ksrc = (const float4*)(g_keyT + (size_t)((n*HH + h)*EE)*SS);

  #pragma unroll
  for (int p = 0; p < 3; p++) {
    const int c0 = 2*p;
    __syncthreads();   // prev epilogue reads done before rewriting below

    for (int idx = tid; idx < 2*TLm*EE; idx += 512) {
      int cc = idx >> 10, off = idx & 1023;
      s_ht2[idx] = g_ht[((size_t)(((c0+cc)*NB + n)*HH + h)*LL + l0)*EE + off];
    }
    if (tid < 2*TLm) {
      int cc = tid >> 4, l = tid & 15;
      s_hsq2[tid] = g_hsq[(size_t)(((c0+cc)*NB + n)*HH + h)*LL + l0 + l];
      s_pi2[tid]  = g_pi[((size_t)((n*HH + h)*LL) + l0 + l)*KK + c0 + cc];
    }

    // prefetch chunk 0 into buffer 0
    float4 pf[4];
    #pragma unroll
    for (int t = 0; t < 4; t++) pf[t] = ksrc[tid + t*512];
    float4* kb = (float4*)s_key;
    #pragma unroll
    for (int t = 0; t < 4; t++) kb[tid + t*512] = pf[t];
    __syncthreads();

    float acc[2][4][8];
    #pragma unroll
    for (int cc = 0; cc < 2; cc++)
      #pragma unroll
      for (int i = 0; i < 4; i++)
        #pragma unroll
        for (int j = 0; j < 8; j++) acc[cc][i][j] = 0.f;

    #pragma unroll 1
    for (int ec = 0; ec < EE/ECm; ec++) {
      if (ec + 1 < EE/ECm) {
        #pragma unroll
        for (int t = 0; t < 4; t++)
          pf[t] = ksrc[(ec+1)*(ECm*SS/4) + tid + t*512];
      }
      const float* kcur = s_key + (ec & 1) * (ECm*SS);
      #pragma unroll
      for (int e = 0; e < ECm; e++) {
        float4 kv0 = *(const float4*)&kcur[e*SS + 4*si];
        float4 kv1 = *(const float4*)&kcur[e*SS + 512 + 4*si];
        float kv[8] = {kv0.x, kv0.y, kv0.z, kv0.w,
                       kv1.x, kv1.y, kv1.z, kv1.w};
        float hv[2][4];
        #pragma unroll
        for (int cc = 0; cc < 2; cc++)
          #pragma unroll
          for (int i = 0; i < 4; i++)
            hv[cc][i] = s_ht2[cc*1024 + (lg*4 + i)*EE + ec*ECm + e];
        #pragma unroll
        for (int cc = 0; cc < 2; cc++)
          #pragma unroll
          for (int i = 0; i < 4; i++)
            #pragma unroll
            for (int j = 0; j < 8; j++)
              acc[cc][i][j] += hv[cc][i] * kv[j];
      }
      if (ec + 1 < EE/ECm) {
        float4* kdst = (float4*)(s_key + ((ec+1) & 1) * (ECm*SS));
        #pragma unroll
        for (int t = 0; t < 4; t++) kdst[tid + t*512] = pf[t];
        __syncthreads();
      }
    }

    // --- epilogue: transform + masked softmax + weighted accumulate ---
    #pragma unroll
    for (int cc = 0; cc < 2; cc++) {
      float ksqv[8];
      {
        float4 k0 = *(const float4*)&s_ksq[4*si];
        float4 k1 = *(const float4*)&s_ksq[512 + 4*si];
        ksqv[0]=k0.x; ksqv[1]=k0.y; ksqv[2]=k0.z; ksqv[3]=k0.w;
        ksqv[4]=k1.x; ksqv[5]=k1.y; ksqv[6]=k1.z; ksqv[7]=k1.w;
      }
      #pragma unroll
      for (int i = 0; i < 4; i++) {
        int l = lg*4 + i;
        float hsqv = s_hsq2[cc*16 + l];
        float4 m0 = *(const float4*)&s_mask[l*SS + 4*si];
        float4 m1 = *(const float4*)&s_mask[l*SS + 512 + 4*si];
        float mkv[8] = {m0.x, m0.y, m0.z, m0.w, m1.x, m1.y, m1.z, m1.w};
        float mm = -3.4e38f;
        #pragma unroll
        for (int j = 0; j < 8; j++) {
          float d  = acc[cc][i][j];
          float ns = hsqv + ksqv[j] - 2.f*d;
          float f  = kfun(c0 + cc, d, ns) + mkv[j];
          acc[cc][i][j] = f;
          mm = fmaxf(mm, f);
        }
        #pragma unroll
        for (int o = 16; o; o >>= 1)
          mm = fmaxf(mm, __shfl_xor_sync(0xffffffffu, mm, o));
        if (lane == 0) s_redm[l*4 + w4] = mm;
      }
      __syncthreads();
      float m[4];
      #pragma unroll
      for (int i = 0; i < 4; i++) {
        int l = lg*4 + i;
        m[i] = fmaxf(fmaxf(s_redm[l*4+0], s_redm[l*4+1]),
                     fmaxf(s_redm[l*4+2], s_redm[l*4+3]));
      }
      #pragma unroll
      for (int i = 0; i < 4; i++) {
        int l = lg*4 + i;
        float z = 0.f;
        #pragma unroll
        for (int j = 0; j < 8; j++) {
          float ev = __expf(acc[cc][i][j] - m[i]);
          acc[cc][i][j] = ev;
          z += ev;
        }
        #pragma unroll
        for (int o = 16; o; o >>= 1) z += __shfl_xor_sync(0xffffffffu, z, o);
        if (lane == 0) s_redz[l*4 + w4] = z;
      }
      __syncthreads();
      #pragma unroll
      for (int i = 0; i < 4; i++) {
        int l = lg*4 + i;
        float Z = s_redz[l*4+0] + s_redz[l*4+1] + s_redz[l*4+2] + s_redz[l*4+3];
        float coef = s_pi2[cc*16 + l] / Z;
        #pragma unroll
        for (int j = 0; j < 8; j++) outacc[i][j] += coef * acc[cc][i][j];
      }
      // note: s_redm/s_redz rewritten next cc only after the sync at loop
      // top (cc=1 path) or pair-loop top sync; the sync after redz above
      // already separates redm reuse.
    }
  }

  // coalesced float4 final write from registers
  size_t ob = (size_t)((n*HH + h)*LL + l0 + lg*4)*SS;
  #pragma unroll
  for (int i = 0; i < 4; i++) {
    *(float4*)&out[ob + (size_t)i*SS + 4*si] =
        make_float4(outacc[i][0], outacc[i][1], outacc[i][2], outacc[i][3]);
    *(float4*)&out[ob + (size_t)i*SS + 512 + 4*si] =
        make_float4(outacc[i][4], outacc[i][5], outacc[i][6], outacc[i][7]);
  }
}

// ---------------------------------------------------------------------------
extern "C" void kernel_launch(void* const* d_in, const int* in_sizes, int n_in,
                              void* d_out, int out_size)
{
  const float* q    = (const float*)d_in[0];  // [2,1024,8,64]
  const float* key  = (const float*)d_in[1];  // [2,1024,8,64]
  const float* mask = (const float*)d_in[2];  // [2,1024,1024]
  const float* klen = (const float*)d_in[3];  // [2,1024]
  const float* M    = (const float*)d_in[4];  // [8,64,6]
  const float* C    = (const float*)d_in[5];  // [6,8,64,64]
  float* out = (float*)d_out;                 // [2,8,1024,1024]
  (void)in_sizes; (void)n_in; (void)out_size;

  cudaFuncSetAttribute(attn_kernel,
      cudaFuncAttributeMaxDynamicSharedMemorySize, SMEM_BYTES);

  dim3 gpre(LL/64, HH, NB*KK), bpre(256);
  precompute_kernel<<<gpre, bpre>>>(q, M, C);
  dim3 gkey(LL/64, HH, NB), bkey(256);
  keyprep_kernel<<<gkey, bkey>>>(key);
  dim3 gmain(LL/TLm, HH, NB), bmain(512);
  attn_kernel<<<gmain, bmain, SMEM_BYTES>>>(mask, klen, out);
}

// round 6
// speedup vs baseline: 1.3149x; 1.3149x over previous
#include <cuda_runtime.h>
#include <math.h>
#include <stdint.h>

#define NB 2
#define LL 1024
#define SS 1024
#define HH 8
#define EE 64
#define KK 6

// Scratch (static device globals: allocation-free rule)
__device__ __align__(16) float g_ht[(size_t)KK*NB*HH*LL*EE];   // htilde[c][n][h][l][e]
__device__ float g_hsq[(size_t)KK*NB*HH*LL];     // ||htilde||^2
__device__ float g_pi[(size_t)NB*HH*LL*KK];      // mixture weights [n][h][l][c]
__device__ __align__(16) float g_keyT[(size_t)NB*HH*EE*SS];    // key transposed [n][h][e][s]
__device__ __align__(16) float g_ksq[(size_t)NB*HH*SS];        // ||key||^2 [n][h][s]

// ---------------------------------------------------------------------------
// Kernel 1: pi = softmax_k(q.M), htilde[c] = tanh(q.C[c]), hsq
// Mapping: lq = tid&63 (row), f0 = (tid>>6)*16 -> sc reads are warp-uniform
// broadcasts (1 wavefront), sq reads stride-65 conflict-free.
// ---------------------------------------------------------------------------
__global__ __launch_bounds__(256) void precompute_kernel(
    const float* __restrict__ q, const float* __restrict__ M,
    const float* __restrict__ C)
{
  int lt = blockIdx.x, h = blockIdx.y;
  int c  = blockIdx.z >> 1;      // z = c*NB + n
  int n  = blockIdx.z & 1;
  int l0 = lt * 64;
  int tid = threadIdx.x;
  __shared__ float sq[64][65];
  __shared__ float sc[64][64];
  __shared__ float sz[64][KK];
  __shared__ float spart[64][4];

  for (int idx = tid; idx < 4096; idx += 256) {
    int l = idx >> 6, e = idx & 63;
    sq[l][e] = q[((size_t)((n*LL + l0 + l)*HH + h))*EE + e];
  }
  for (int idx = tid; idx < 4096; idx += 256)
    sc[idx >> 6][idx & 63] = C[(size_t)(c*HH + h)*4096 + idx];
  __syncthreads();

  if (c == 0) {  // pi computed once (by the c==0 blocks)
    for (int t = tid; t < 64*KK; t += 256) {
      int l = t / KK, k = t % KK;
      float a = 0.f;
      for (int e = 0; e < EE; e++) a += sq[l][e] * M[(h*EE + e)*KK + k];
      sz[l][k] = a;
    }
    __syncthreads();
    if (tid < 64) {
      float mx = sz[tid][0];
      #pragma unroll
      for (int k = 1; k < KK; k++) mx = fmaxf(mx, sz[tid][k]);
      float s = 0.f, ev[KK];
      #pragma unroll
      for (int k = 0; k < KK; k++) { ev[k] = __expf(sz[tid][k] - mx); s += ev[k]; }
      float inv = 1.f / s;
      #pragma unroll
      for (int k = 0; k < KK; k++)
        g_pi[((size_t)((n*HH + h)*LL) + l0 + tid)*KK + k] = ev[k]*inv;
    }
  }

  int lq = tid & 63;            // row (warp-consecutive)
  int f0 = (tid >> 6) * 16;     // 16 consecutive f, uniform per warp
  float a[16];
  #pragma unroll
  for (int j = 0; j < 16; j++) a[j] = 0.f;
  for (int e = 0; e < EE; e++) {
    float qv = sq[lq][e];
    const float4* crow = (const float4*)&sc[e][f0];
    #pragma unroll
    for (int v = 0; v < 4; v++) {
      float4 cv = crow[v];
      a[v*4+0] += qv * cv.x;
      a[v*4+1] += qv * cv.y;
      a[v*4+2] += qv * cv.z;
      a[v*4+3] += qv * cv.w;
    }
  }
  size_t htbase = ((size_t)((c*NB + n)*HH + h)*LL + l0 + lq)*EE + f0;
  float4* hdst = (float4*)&g_ht[htbase];
  float ssq = 0.f;
  #pragma unroll
  for (int v = 0; v < 4; v++) {   // short tanh live ranges
    float4 o;
    o.x = tanhf(a[v*4+0]); ssq += o.x*o.x;
    o.y = tanhf(a[v*4+1]); ssq += o.y*o.y;
    o.z = tanhf(a[v*4+2]); ssq += o.z*o.z;
    o.w = tanhf(a[v*4+3]); ssq += o.w*o.w;
    hdst[v] = o;
  }
  spart[lq][tid >> 6] = ssq;
  __syncthreads();
  if (tid < 64)
    g_hsq[(size_t)((c*NB + n)*HH + h)*LL + l0 + tid] =
      spart[tid][0] + spart[tid][1] + spart[tid][2] + spart[tid][3];
}

// ---------------------------------------------------------------------------
// Kernel 2: key transpose -> g_keyT[n][h][e][s], and ksq
// ---------------------------------------------------------------------------
__global__ __launch_bounds__(256) void keyprep_kernel(const float* __restrict__ key)
{
  int st = blockIdx.x, h = blockIdx.y, n = blockIdx.z;
  int s0 = st * 64;
  int tid = threadIdx.x;
  __shared__ float sk[64][65];
  for (int idx = tid; idx < 4096; idx += 256) {
    int s = idx >> 6, e = idx & 63;
    sk[s][e] = key[((size_t)((n*SS + s0 + s)*HH + h))*EE + e];
  }
  __syncthreads();
  for (int idx = tid; idx < 4096; idx += 256) {
    int e = idx >> 6, s = idx & 63;
    g_keyT[((size_t)((n*HH + h)*EE) + e)*SS + s0 + s] = sk[s][e];
  }
  if (tid < 64) {
    float a = 0.f;
    #pragma unroll
    for (int e = 0; e < EE; e++) a += sk[tid][e] * sk[tid][e];
    g_ksq[(size_t)(n*HH + h)*SS + s0 + tid] = a;
  }
}

// ---------------------------------------------------------------------------
// Kernel 3: fused logits + softmax + mixture.
// 256-thread CTAs, 4 l-rows x 1024 s per CTA, 3 codes per key pass (2 passes).
// 2 CTAs/SM -> epilogue of one CTA overlaps mainloop of the other.
// cp.async double-buffered key chunks (8 e per chunk).
// ---------------------------------------------------------------------------
#define TLm 4
#define ECm 8
#define PCC 3      // codes per pass

// smem float offsets
#define SMO_KEY   0          // 2 * 8192 = 16384
#define SMO_MASK  16384      // 4096
#define SMO_HT    20480      // PCC*TLm*EE = 768
#define SMO_KSQ   21248      // 1024
#define SMO_HSQ   22272      // 12 (pad 16)
#define SMO_PI    22288      // 12 (pad 16)
#define SMO_REDM  22304      // 16
#define SMO_REDZ  22320      // 16
#define SMEM_FLOATS 22336
#define SMEM_BYTES (SMEM_FLOATS*4)

__device__ __forceinline__ void cp_async16(uint32_t dst, const float4* src) {
  asm volatile("cp.async.cg.shared.global [%0], [%1], 16;\n" :: "r"(dst), "l"(src));
}
__device__ __forceinline__ void cp_commit() {
  asm volatile("cp.async.commit_group;\n");
}
template<int N> __device__ __forceinline__ void cp_wait() {
  asm volatile("cp.async.wait_group %0;\n" :: "n"(N));
}

__device__ __forceinline__ float kfun(int c, float d, float ns) {
  if (c == 0) return d;                                   // 'L'
  if (c == 1) return -__logf(1.f + ns);                   // 'O' (ns>=0)
  if (c == 2) return -ns;                                 // 'P'
  if (c == 3) { float t = d + 1.f; return t * t; }        // 'Y'
  if (c == 4) return __expf(-0.5f * ns);                  // 'R'
  return __cosf(ns) * __expf(-ns);                        // 'W'
}

__global__ __launch_bounds__(256, 2) void attn_kernel(
    const float* __restrict__ mask, const float* __restrict__ keylen,
    float* __restrict__ out)
{
  extern __shared__ float sm[];
  float* s_key  = sm + SMO_KEY;
  float* s_mask = sm + SMO_MASK;
  float* s_ht   = sm + SMO_HT;
  float* s_ksq  = sm + SMO_KSQ;
  float* s_hsq  = sm + SMO_HSQ;
  float* s_pi   = sm + SMO_PI;
  float* s_redm = sm + SMO_REDM;
  float* s_redz = sm + SMO_REDZ;
  uint32_t skey_u32 = (uint32_t)__cvta_generic_to_shared(s_key);

  int lt = blockIdx.x, h = blockIdx.y, n = blockIdx.z;
  int l0 = lt * TLm;
  int tid  = threadIdx.x;
  int lg   = tid >> 7;        // 0..1 -> rows lg*2 .. lg*2+1
  int si   = tid & 127;       // s = 4*si+r  and  512+4*si+r
  int lane = tid & 31;
  int w4   = si >> 5;

  for (int s = tid; s < SS; s += 256)
    s_ksq[s] = g_ksq[(size_t)(n*HH + h)*SS + s];

  // mask tile + keylen folded (reused by all 6 codes)
  {
    const float4* msrc  = (const float4*)(mask + ((size_t)n*LL + l0)*SS);
    const float4* klsrc = (const float4*)(keylen + (size_t)n*SS);
    float4* mdst = (float4*)s_mask;
    #pragma unroll
    for (int t = 0; t < TLm*SS/4/256; t++) {
      int idx = tid + t*256;
      float4 mv = msrc[idx];
      float4 kv = klsrc[idx & 255];
      mdst[idx] = make_float4(mv.x+kv.x, mv.y+kv.y, mv.z+kv.z, mv.w+kv.w);
    }
  }

  float outacc[2][8];
  #pragma unroll
  for (int i = 0; i < 2; i++)
    #pragma unroll
    for (int j = 0; j < 8; j++) outacc[i][j] = 0.f;

  const float4* ksrc = (const float4*)(g_keyT + (size_t)((n*HH + h)*EE)*SS);

  #pragma unroll 1
  for (int p = 0; p < 2; p++) {
    const int c0 = PCC*p;
    __syncthreads();   // prev pass fully done before rewriting s_ht / s_key

    for (int idx = tid; idx < PCC*TLm*EE; idx += 256) {
      int cc = idx >> 8, off = idx & 255;   // TLm*EE = 256
      s_ht[idx] = g_ht[((size_t)(((c0+cc)*NB + n)*HH + h)*LL + l0)*EE + off];
    }
    if (tid < PCC*TLm) {
      int cc = tid >> 2, l = tid & 3;
      s_hsq[tid] = g_hsq[(size_t)(((c0+cc)*NB + n)*HH + h)*LL + l0 + l];
      s_pi[tid]  = g_pi[((size_t)((n*HH + h)*LL) + l0 + l)*KK + c0 + cc];
    }

    // issue chunk 0
    #pragma unroll
    for (int t = 0; t < 8; t++) {
      int idx = tid + t*256;
      cp_async16(skey_u32 + idx*16, ksrc + idx);
    }
    cp_commit();

    float acc[PCC][2][8];
    #pragma unroll
    for (int cc = 0; cc < PCC; cc++)
      #pragma unroll
      for (int i = 0; i < 2; i++)
        #pragma unroll
        for (int j = 0; j < 8; j++) acc[cc][i][j] = 0.f;

    #pragma unroll 1
    for (int ec = 0; ec < EE/ECm; ec++) {
      if (ec + 1 < EE/ECm) {
        uint32_t dst = skey_u32 + ((ec+1) & 1) * (ECm*SS*4);
        const float4* src = ksrc + (ec+1)*(ECm*SS/4);
        #pragma unroll
        for (int t = 0; t < 8; t++) {
          int idx = tid + t*256;
          cp_async16(dst + idx*16, src + idx);
        }
        cp_commit();
        cp_wait<1>();
      } else {
        cp_wait<0>();
      }
      __syncthreads();
      const float* kcur = s_key + (ec & 1) * (ECm*SS);
      #pragma unroll
      for (int e = 0; e < ECm; e++) {
        float4 kv0 = *(const float4*)&kcur[e*SS + 4*si];
        float4 kv1 = *(const float4*)&kcur[e*SS + 512 + 4*si];
        float kv[8] = {kv0.x, kv0.y, kv0.z, kv0.w,
                       kv1.x, kv1.y, kv1.z, kv1.w};
        float hv[PCC][2];
        #pragma unroll
        for (int cc = 0; cc < PCC; cc++)
          #pragma unroll
          for (int i = 0; i < 2; i++)
            hv[cc][i] = s_ht[cc*(TLm*EE) + (lg*2 + i)*EE + ec*ECm + e];
        #pragma unroll
        for (int cc = 0; cc < PCC; cc++)
          #pragma unroll
          for (int i = 0; i < 2; i++)
            #pragma unroll
            for (int j = 0; j < 8; j++)
              acc[cc][i][j] += hv[cc][i] * kv[j];
      }
      __syncthreads();   // compute done before buffer overwritten next iter
    }

    // --- epilogue: transform + masked softmax + weighted accumulate ---
    float ksqv[8];
    {
      float4 k0 = *(const float4*)&s_ksq[4*si];
      float4 k1 = *(const float4*)&s_ksq[512 + 4*si];
      ksqv[0]=k0.x; ksqv[1]=k0.y; ksqv[2]=k0.z; ksqv[3]=k0.w;
      ksqv[4]=k1.x; ksqv[5]=k1.y; ksqv[6]=k1.z; ksqv[7]=k1.w;
    }
    #pragma unroll
    for (int cc = 0; cc < PCC; cc++) {
      #pragma unroll
      for (int i = 0; i < 2; i++) {
        int l = lg*2 + i;
        float hsqv = s_hsq[cc*TLm + l];
        float4 m0 = *(const float4*)&s_mask[l*SS + 4*si];
        float4 m1 = *(const float4*)&s_mask[l*SS + 512 + 4*si];
        float mkv[8] = {m0.x, m0.y, m0.z, m0.w, m1.x, m1.y, m1.z, m1.w};
        float mm = -3.4e38f;
        #pragma unroll
        for (int j = 0; j < 8; j++) {
          float d  = acc[cc][i][j];
          float ns = hsqv + ksqv[j] - 2.f*d;
          float f  = kfun(c0 + cc, d, ns) + mkv[j];
          acc[cc][i][j] = f;
          mm = fmaxf(mm, f);
        }
        #pragma unroll
        for (int o = 16; o; o >>= 1)
          mm = fmaxf(mm, __shfl_xor_sync(0xffffffffu, mm, o));
        if (lane == 0) s_redm[l*4 + w4] = mm;
      }
      __syncthreads();
      #pragma unroll
      for (int i = 0; i < 2; i++) {
        int l = lg*2 + i;
        float m = fmaxf(fmaxf(s_redm[l*4+0], s_redm[l*4+1]),
                        fmaxf(s_redm[l*4+2], s_redm[l*4+3]));
        float z = 0.f;
        #pragma unroll
        for (int j = 0; j < 8; j++) {
          float ev = __expf(acc[cc][i][j] - m);
          acc[cc][i][j] = ev;
          z += ev;
        }
        #pragma unroll
        for (int o = 16; o; o >>= 1) z += __shfl_xor_sync(0xffffffffu, z, o);
        if (lane == 0) s_redz[l*4 + w4] = z;
      }
      __syncthreads();
      #pragma unroll
      for (int i = 0; i < 2; i++) {
        int l = lg*2 + i;
        float Z = s_redz[l*4+0] + s_redz[l*4+1] + s_redz[l*4+2] + s_redz[l*4+3];
        float coef = s_pi[cc*TLm + l] / Z;
        #pragma unroll
        for (int j = 0; j < 8; j++) outacc[i][j] += coef * acc[cc][i][j];
      }
      // redm rewrite of next cc is separated by the redz sync above;
      // redz rewrite is separated by next cc's redm sync.
    }
  }

  // coalesced float4 final write from registers
  size_t ob = (size_t)((n*HH + h)*LL + l0 + lg*2)*SS;
  #pragma unroll
  for (int i = 0; i < 2; i++) {
    *(float4*)&out[ob + (size_t)i*SS + 4*si] =
        make_float4(outacc[i][0], outacc[i][1], outacc[i][2], outacc[i][3]);
    *(float4*)&out[ob + (size_t)i*SS + 512 + 4*si] =
        make_float4(outacc[i][4], outacc[i][5], outacc[i][6], outacc[i][7]);
  }
}

// ---------------------------------------------------------------------------
extern "C" void kernel_launch(void* const* d_in, const int* in_sizes, int n_in,
                              void* d_out, int out_size)
{
  const float* q    = (const float*)d_in[0];  // [2,1024,8,64]
  const float* key  = (const float*)d_in[1];  // [2,1024,8,64]
  const float* mask = (const float*)d_in[2];  // [2,1024,1024]
  const float* klen = (const float*)d_in[3];  // [2,1024]
  const float* M    = (const float*)d_in[4];  // [8,64,6]
  const float* C    = (const float*)d_in[5];  // [6,8,64,64]
  float* out = (float*)d_out;                 // [2,8,1024,1024]
  (void)in_sizes; (void)n_in; (void)out_size;

  cudaFuncSetAttribute(attn_kernel,
      cudaFuncAttributeMaxDynamicSharedMemorySize, SMEM_BYTES);

  dim3 gpre(LL/64, HH, NB*KK), bpre(256);
  precompute_kernel<<<gpre, bpre>>>(q, M, C);
  dim3 gkey(LL/64, HH, NB), bkey(256);
  keyprep_kernel<<<gkey, bkey>>>(key);
  dim3 gmain(LL/TLm, HH, NB), bmain(256);
  attn_kernel<<<gmain, bmain, SMEM_BYTES>>>(mask, klen, out);
}

// round 7
// speedup vs baseline: 1.4011x; 1.0656x over previous
#include <cuda_runtime.h>
#include <math.h>
#include <stdint.h>

#define NB 2
#define LL 1024
#define SS 1024
#define HH 8
#define EE 64
#define KK 6

// Scratch (static device globals: allocation-free rule)
__device__ __align__(16) float g_ht[(size_t)KK*NB*HH*LL*EE];   // htilde[c][n][h][l][e]
__device__ float g_hsq[(size_t)KK*NB*HH*LL];     // ||htilde||^2
__device__ float g_pi[(size_t)NB*HH*LL*KK];      // mixture weights [n][h][l][c]
__device__ __align__(16) float g_keyT[(size_t)NB*HH*EE*SS];    // key transposed [n][h][e][s]
__device__ __align__(16) float g_ksq[(size_t)NB*HH*SS];        // ||key||^2 [n][h][s]

// ---- packed fp32x2 helpers (Blackwell FFMA2) -------------------------------
__device__ __forceinline__ uint64_t ffma2(uint64_t a, uint64_t b, uint64_t c) {
  uint64_t d;
  asm("fma.rn.f32x2 %0, %1, %2, %3;" : "=l"(d) : "l"(a), "l"(b), "l"(c));
  return d;
}
__device__ __forceinline__ uint64_t bcast2(float v) {
  uint64_t d; uint32_t r = __float_as_uint(v);
  asm("mov.b64 %0, {%1, %1};" : "=l"(d) : "r"(r));
  return d;
}
__device__ __forceinline__ float lo32(uint64_t a) {
  return __uint_as_float((uint32_t)a);
}
__device__ __forceinline__ float hi32(uint64_t a) {
  return __uint_as_float((uint32_t)(a >> 32));
}

// ---------------------------------------------------------------------------
// Kernel 1: pi = softmax_k(q.M), htilde[c] = tanh(q.C[c]), hsq
// lq = tid&63 (row), f0 = (tid>>6)*16 -> sc reads warp-uniform broadcasts.
// Inner GEMM in packed FFMA2.
// ---------------------------------------------------------------------------
__global__ __launch_bounds__(256) void precompute_kernel(
    const float* __restrict__ q, const float* __restrict__ M,
    const float* __restrict__ C)
{
  int lt = blockIdx.x, h = blockIdx.y;
  int c  = blockIdx.z >> 1;      // z = c*NB + n
  int n  = blockIdx.z & 1;
  int l0 = lt * 64;
  int tid = threadIdx.x;
  __shared__ float sq[64][65];
  __shared__ __align__(16) float sc[64][64];
  __shared__ float sz[64][KK];
  __shared__ float spart[64][4];

  for (int idx = tid; idx < 4096; idx += 256) {
    int l = idx >> 6, e = idx & 63;
    sq[l][e] = q[((size_t)((n*LL + l0 + l)*HH + h))*EE + e];
  }
  for (int idx = tid; idx < 4096; idx += 256)
    sc[idx >> 6][idx & 63] = C[(size_t)(c*HH + h)*4096 + idx];
  __syncthreads();

  if (c == 0) {  // pi computed once (by the c==0 blocks)
    for (int t = tid; t < 64*KK; t += 256) {
      int l = t / KK, k = t % KK;
      float a = 0.f;
      for (int e = 0; e < EE; e++) a += sq[l][e] * M[(h*EE + e)*KK + k];
      sz[l][k] = a;
    }
    __syncthreads();
    if (tid < 64) {
      float mx = sz[tid][0];
      #pragma unroll
      for (int k = 1; k < KK; k++) mx = fmaxf(mx, sz[tid][k]);
      float s = 0.f, ev[KK];
      #pragma unroll
      for (int k = 0; k < KK; k++) { ev[k] = __expf(sz[tid][k] - mx); s += ev[k]; }
      float inv = 1.f / s;
      #pragma unroll
      for (int k = 0; k < KK; k++)
        g_pi[((size_t)((n*HH + h)*LL) + l0 + tid)*KK + k] = ev[k]*inv;
    }
  }

  int lq = tid & 63;            // row (warp-consecutive)
  int f0 = (tid >> 6) * 16;     // 16 consecutive f, uniform per warp
  uint64_t a2[8];
  #pragma unroll
  for (int j = 0; j < 8; j++) a2[j] = 0;
  for (int e = 0; e < EE; e++) {
    uint64_t qp = bcast2(sq[lq][e]);
    const uint64_t* crow = (const uint64_t*)&sc[e][f0];
    #pragma unroll
    for (int v = 0; v < 8; v++)
      a2[v] = ffma2(qp, crow[v], a2[v]);
  }
  size_t htbase = ((size_t)((c*NB + n)*HH + h)*LL + l0 + lq)*EE + f0;
  float4* hdst = (float4*)&g_ht[htbase];
  float ssq = 0.f;
  #pragma unroll
  for (int v = 0; v < 4; v++) {   // short tanh live ranges
    float4 o;
    o.x = tanhf(lo32(a2[v*2+0])); ssq += o.x*o.x;
    o.y = tanhf(hi32(a2[v*2+0])); ssq += o.y*o.y;
    o.z = tanhf(lo32(a2[v*2+1])); ssq += o.z*o.z;
    o.w = tanhf(hi32(a2[v*2+1])); ssq += o.w*o.w;
    hdst[v] = o;
  }
  spart[lq][tid >> 6] = ssq;
  __syncthreads();
  if (tid < 64)
    g_hsq[(size_t)((c*NB + n)*HH + h)*LL + l0 + tid] =
      spart[tid][0] + spart[tid][1] + spart[tid][2] + spart[tid][3];
}

// ---------------------------------------------------------------------------
// Kernel 2: key transpose -> g_keyT[n][h][e][s], and ksq
// ---------------------------------------------------------------------------
__global__ __launch_bounds__(256) void keyprep_kernel(const float* __restrict__ key)
{
  int st = blockIdx.x, h = blockIdx.y, n = blockIdx.z;
  int s0 = st * 64;
  int tid = threadIdx.x;
  __shared__ float sk[64][65];
  for (int idx = tid; idx < 4096; idx += 256) {
    int s = idx >> 6, e = idx & 63;
    sk[s][e] = key[((size_t)((n*SS + s0 + s)*HH + h))*EE + e];
  }
  __syncthreads();
  for (int idx = tid; idx < 4096; idx += 256) {
    int e = idx >> 6, s = idx & 63;
    g_keyT[((size_t)((n*HH + h)*EE) + e)*SS + s0 + s] = sk[s][e];
  }
  if (tid < 64) {
    float a = 0.f;
    #pragma unroll
    for (int e = 0; e < EE; e++) a += sk[tid][e] * sk[tid][e];
    g_ksq[(size_t)(n*HH + h)*SS + s0 + tid] = a;
  }
}

// ---------------------------------------------------------------------------
// Kernel 3: fused logits + softmax + mixture.
// 256-thread CTAs, 4 l-rows x 1024 s per CTA, 3 codes per key pass (2 passes).
// 2 CTAs/SM; cp.async double-buffered key chunks; packed FFMA2 mainloop
// (lanes = s-pairs; kv pairs come free from the 16B smem loads, hv is a
// broadcast LDS.32 duplicated via mov.b64).
// ---------------------------------------------------------------------------
#define TLm 4
#define ECm 8
#define PCC 3      // codes per pass

// smem float offsets
#define SMO_KEY   0          // 2 * 8192 = 16384
#define SMO_MASK  16384      // 4096
#define SMO_HT    20480      // PCC*TLm*EE = 768
#define SMO_KSQ   21248      // 1024
#define SMO_HSQ   22272      // 12 (pad 16)
#define SMO_PI    22288      // 12 (pad 16)
#define SMO_REDM  22304      // 16
#define SMO_REDZ  22320      // 16
#define SMEM_FLOATS 22336
#define SMEM_BYTES (SMEM_FLOATS*4)

__device__ __forceinline__ void cp_async16(uint32_t dst, const float4* src) {
  asm volatile("cp.async.cg.shared.global [%0], [%1], 16;\n" :: "r"(dst), "l"(src));
}
__device__ __forceinline__ void cp_commit() {
  asm volatile("cp.async.commit_group;\n");
}
template<int N> __device__ __forceinline__ void cp_wait() {
  asm volatile("cp.async.wait_group %0;\n" :: "n"(N));
}

__device__ __forceinline__ float kfun(int c, float d, float ns) {
  if (c == 0) return d;                                   // 'L'
  if (c == 1) return -__logf(1.f + ns);                   // 'O' (ns>=0)
  if (c == 2) return -ns;                                 // 'P'
  if (c == 3) { float t = d + 1.f; return t * t; }        // 'Y'
  if (c == 4) return __expf(-0.5f * ns);                  // 'R'
  return __cosf(ns) * __expf(-ns);                        // 'W'
}

__global__ __launch_bounds__(256, 2) void attn_kernel(
    const float* __restrict__ mask, const float* __restrict__ keylen,
    float* __restrict__ out)
{
  extern __shared__ float sm[];
  float* s_key  = sm + SMO_KEY;
  float* s_mask = sm + SMO_MASK;
  float* s_ht   = sm + SMO_HT;
  float* s_ksq  = sm + SMO_KSQ;
  float* s_hsq  = sm + SMO_HSQ;
  float* s_pi   = sm + SMO_PI;
  float* s_redm = sm + SMO_REDM;
  float* s_redz = sm + SMO_REDZ;
  uint32_t skey_u32 = (uint32_t)__cvta_generic_to_shared(s_key);

  int lt = blockIdx.x, h = blockIdx.y, n = blockIdx.z;
  int l0 = lt * TLm;
  int tid  = threadIdx.x;
  int lg   = tid >> 7;        // 0..1 -> rows lg*2 .. lg*2+1
  int si   = tid & 127;       // s = 4*si+r  and  512+4*si+r
  int lane = tid & 31;
  int w4   = si >> 5;

  for (int s = tid; s < SS; s += 256)
    s_ksq[s] = g_ksq[(size_t)(n*HH + h)*SS + s];

  // mask tile + keylen folded (reused by all 6 codes)
  {
    const float4* msrc  = (const float4*)(mask + ((size_t)n*LL + l0)*SS);
    const float4* klsrc = (const float4*)(keylen + (size_t)n*SS);
    float4* mdst = (float4*)s_mask;
    #pragma unroll
    for (int t = 0; t < TLm*SS/4/256; t++) {
      int idx = tid + t*256;
      float4 mv = msrc[idx];
      float4 kv = klsrc[idx & 255];
      mdst[idx] = make_float4(mv.x+kv.x, mv.y+kv.y, mv.z+kv.z, mv.w+kv.w);
    }
  }

  float outacc[2][8];
  #pragma unroll
  for (int i = 0; i < 2; i++)
    #pragma unroll
    for (int j = 0; j < 8; j++) outacc[i][j] = 0.f;

  const float4* ksrc = (const float4*)(g_keyT + (size_t)((n*HH + h)*EE)*SS);

  #pragma unroll 1
  for (int p = 0; p < 2; p++) {
    const int c0 = PCC*p;
    __syncthreads();   // prev pass fully done before rewriting s_ht / s_key

    for (int idx = tid; idx < PCC*TLm*EE; idx += 256) {
      int cc = idx >> 8, off = idx & 255;   // TLm*EE = 256
      s_ht[idx] = g_ht[((size_t)(((c0+cc)*NB + n)*HH + h)*LL + l0)*EE + off];
    }
    if (tid < PCC*TLm) {
      int cc = tid >> 2, l = tid & 3;
      s_hsq[tid] = g_hsq[(size_t)(((c0+cc)*NB + n)*HH + h)*LL + l0 + l];
      s_pi[tid]  = g_pi[((size_t)((n*HH + h)*LL) + l0 + l)*KK + c0 + cc];
    }

    // issue chunk 0
    #pragma unroll
    for (int t = 0; t < 8; t++) {
      int idx = tid + t*256;
      cp_async16(skey_u32 + idx*16, ksrc + idx);
    }
    cp_commit();

    // packed accumulators: [code][row][s-pair], pair = (2 consecutive s)
    uint64_t acc2[PCC][2][4];
    #pragma unroll
    for (int cc = 0; cc < PCC; cc++)
      #pragma unroll
      for (int i = 0; i < 2; i++)
        #pragma unroll
        for (int jp = 0; jp < 4; jp++) acc2[cc][i][jp] = 0;

    #pragma unroll 1
    for (int ec = 0; ec < EE/ECm; ec++) {
      if (ec + 1 < EE/ECm) {
        uint32_t dst = skey_u32 + ((ec+1) & 1) * (ECm*SS*4);
        const float4* src = ksrc + (ec+1)*(ECm*SS/4);
        #pragma unroll
        for (int t = 0; t < 8; t++) {
          int idx = tid + t*256;
          cp_async16(dst + idx*16, src + idx);
        }
        cp_commit();
        cp_wait<1>();
      } else {
        cp_wait<0>();
      }
      __syncthreads();
      const float* kcur = s_key + (ec & 1) * (ECm*SS);
      #pragma unroll
      for (int e = 0; e < ECm; e++) {
        // kv: two 16B loads = 4 packed s-pairs
        ulonglong2 kq0 = *(const ulonglong2*)&kcur[e*SS + 4*si];
        ulonglong2 kq1 = *(const ulonglong2*)&kcur[e*SS + 512 + 4*si];
        uint64_t kvp[4] = {kq0.x, kq0.y, kq1.x, kq1.y};
        #pragma unroll
        for (int cc = 0; cc < PCC; cc++)
          #pragma unroll
          for (int i = 0; i < 2; i++) {
            uint64_t hp = bcast2(s_ht[cc*(TLm*EE) + (lg*2 + i)*EE + ec*ECm + e]);
            #pragma unroll
            for (int jp = 0; jp < 4; jp++)
              acc2[cc][i][jp] = ffma2(hp, kvp[jp], acc2[cc][i][jp]);
          }
      }
      __syncthreads();   // compute done before buffer overwritten next iter
    }

    // --- epilogue: transform + masked softmax + weighted accumulate ---
    float ksqv[8];
    {
      float4 k0 = *(const float4*)&s_ksq[4*si];
      float4 k1 = *(const float4*)&s_ksq[512 + 4*si];
      ksqv[0]=k0.x; ksqv[1]=k0.y; ksqv[2]=k0.z; ksqv[3]=k0.w;
      ksqv[4]=k1.x; ksqv[5]=k1.y; ksqv[6]=k1.z; ksqv[7]=k1.w;
    }
    #pragma unroll
    for (int cc = 0; cc < PCC; cc++) {
      float acc[2][8];
      #pragma unroll
      for (int i = 0; i < 2; i++)
        #pragma unroll
        for (int jp = 0; jp < 4; jp++) {
          acc[i][2*jp+0] = lo32(acc2[cc][i][jp]);
          acc[i][2*jp+1] = hi32(acc2[cc][i][jp]);
        }
      #pragma unroll
      for (int i = 0; i < 2; i++) {
        int l = lg*2 + i;
        float hsqv = s_hsq[cc*TLm + l];
        float4 m0 = *(const float4*)&s_mask[l*SS + 4*si];
        float4 m1 = *(const float4*)&s_mask[l*SS + 512 + 4*si];
        float mkv[8] = {m0.x, m0.y, m0.z, m0.w, m1.x, m1.y, m1.z, m1.w};
        float mm = -3.4e38f;
        #pragma unroll
        for (int j = 0; j < 8; j++) {
          float d  = acc[i][j];
          float ns = hsqv + ksqv[j] - 2.f*d;
          float f  = kfun(c0 + cc, d, ns) + mkv[j];
          acc[i][j] = f;
          mm = fmaxf(mm, f);
        }
        #pragma unroll
        for (int o = 16; o; o >>= 1)
          mm = fmaxf(mm, __shfl_xor_sync(0xffffffffu, mm, o));
        if (lane == 0) s_redm[l*4 + w4] = mm;
      }
      __syncthreads();
      #pragma unroll
      for (int i = 0; i < 2; i++) {
        int l = lg*2 + i;
        float m = fmaxf(fmaxf(s_redm[l*4+0], s_redm[l*4+1]),
                        fmaxf(s_redm[l*4+2], s_redm[l*4+3]));
        float z = 0.f;
        #pragma unroll
        for (int j = 0; j < 8; j++) {
          float ev = __expf(acc[i][j] - m);
          acc[i][j] = ev;
          z += ev;
        }
        #pragma unroll
        for (int o = 16; o; o >>= 1) z += __shfl_xor_sync(0xffffffffu, z, o);
        if (lane == 0) s_redz[l*4 + w4] = z;
      }
      __syncthreads();
      #pragma unroll
      for (int i = 0; i < 2; i++) {
        int l = lg*2 + i;
        float Z = s_redz[l*4+0] + s_redz[l*4+1] + s_redz[l*4+2] + s_redz[l*4+3];
        float coef = s_pi[cc*TLm + l] / Z;
        #pragma unroll
        for (int j = 0; j < 8; j++) outacc[i][j] += coef * acc[i][j];
      }
      // redm rewrite of next cc separated by the redz sync above.
    }
  }

  // coalesced float4 final write from registers
  size_t ob = (size_t)((n*HH + h)*LL + l0 + lg*2)*SS;
  #pragma unroll
  for (int i = 0; i < 2; i++) {
    *(float4*)&out[ob + (size_t)i*SS + 4*si] =
        make_float4(outacc[i][0], outacc[i][1], outacc[i][2], outacc[i][3]);
    *(float4*)&out[ob + (size_t)i*SS + 512 + 4*si] =
        make_float4(outacc[i][4], outacc[i][5], outacc[i][6], outacc[i][7]);
  }
}

// ---------------------------------------------------------------------------
extern "C" void kernel_launch(void* const* d_in, const int* in_sizes, int n_in,
                              void* d_out, int out_size)
{
  const float* q    = (const float*)d_in[0];  // [2,1024,8,64]
  const float* key  = (const float*)d_in[1];  // [2,1024,8,64]
  const float* mask = (const float*)d_in[2];  // [2,1024,1024]
  const float* klen = (const float*)d_in[3];  // [2,1024]
  const float* M    = (const float*)d_in[4];  // [8,64,6]
  const float* C    = (const float*)d_in[5];  // [6,8,64,64]
  float* out = (float*)d_out;                 // [2,8,1024,1024]
  (void)in_sizes; (void)n_in; (void)out_size;

  cudaFuncSetAttribute(attn_kernel,
      cudaFuncAttributeMaxDynamicSharedMemorySize, SMEM_BYTES);

  dim3 gpre(LL/64, HH, NB*KK), bpre(256);
  precompute_kernel<<<gpre, bpre>>>(q, M, C);
  dim3 gkey(LL/64, HH, NB), bkey(256);
  keyprep_kernel<<<gkey, bkey>>>(key);
  dim3 gmain(LL/TLm, HH, NB), bmain(256);
  attn_kernel<<<gmain, bmain, SMEM_BYTES>>>(mask, klen, out);
}

// round 8
// speedup vs baseline: 1.4117x; 1.0075x over previous
#include <cuda_runtime.h>
#include <math.h>
#include <stdint.h>

#define NB 2
#define LL 1024
#define SS 1024
#define HH 8
#define EE 64
#define KK 6

// Scratch (static device globals: allocation-free rule)
__device__ __align__(16) float g_ht[(size_t)KK*NB*HH*LL*EE];   // htilde[c][n][h][l][e]
__device__ float g_hsq[(size_t)KK*NB*HH*LL];     // ||htilde||^2
__device__ float g_pi[(size_t)NB*HH*LL*KK];      // mixture weights [n][h][l][c]
__device__ __align__(16) float g_keyT[(size_t)NB*HH*EE*SS];    // key transposed [n][h][e][s]
__device__ __align__(16) float g_ksq[(size_t)NB*HH*SS];        // ||key||^2 [n][h][s]

// ---- packed fp32x2 helpers (Blackwell FFMA2) -------------------------------
__device__ __forceinline__ uint64_t ffma2(uint64_t a, uint64_t b, uint64_t c) {
  uint64_t d;
  asm("fma.rn.f32x2 %0, %1, %2, %3;" : "=l"(d) : "l"(a), "l"(b), "l"(c));
  return d;
}
__device__ __forceinline__ uint64_t bcast2(float v) {
  uint64_t d; uint32_t r = __float_as_uint(v);
  asm("mov.b64 %0, {%1, %1};" : "=l"(d) : "r"(r));
  return d;
}
__device__ __forceinline__ float lo32(uint64_t a) {
  return __uint_as_float((uint32_t)a);
}
__device__ __forceinline__ float hi32(uint64_t a) {
  return __uint_as_float((uint32_t)(a >> 32));
}

// ---------------------------------------------------------------------------
// Kernel 1: pi = softmax_k(q.M), htilde[c] = tanh(q.C[c]), hsq
// lq = tid&63 (row), f0 = (tid>>6)*16 -> sc reads warp-uniform broadcasts.
// Inner GEMM in packed FFMA2.
// ---------------------------------------------------------------------------
__global__ __launch_bounds__(256) void precompute_kernel(
    const float* __restrict__ q, const float* __restrict__ M,
    const float* __restrict__ C)
{
  int lt = blockIdx.x, h = blockIdx.y;
  int c  = blockIdx.z >> 1;      // z = c*NB + n
  int n  = blockIdx.z & 1;
  int l0 = lt * 64;
  int tid = threadIdx.x;
  __shared__ float sq[64][65];
  __shared__ __align__(16) float sc[64][64];
  __shared__ float sz[64][KK];
  __shared__ float spart[64][4];

  for (int idx = tid; idx < 4096; idx += 256) {
    int l = idx >> 6, e = idx & 63;
    sq[l][e] = q[((size_t)((n*LL + l0 + l)*HH + h))*EE + e];
  }
  for (int idx = tid; idx < 4096; idx += 256)
    sc[idx >> 6][idx & 63] = C[(size_t)(c*HH + h)*4096 + idx];
  __syncthreads();

  if (c == 0) {  // pi computed once (by the c==0 blocks)
    for (int t = tid; t < 64*KK; t += 256) {
      int l = t / KK, k = t % KK;
      float a = 0.f;
      for (int e = 0; e < EE; e++) a += sq[l][e] * M[(h*EE + e)*KK + k];
      sz[l][k] = a;
    }
    __syncthreads();
    if (tid < 64) {
      float mx = sz[tid][0];
      #pragma unroll
      for (int k = 1; k < KK; k++) mx = fmaxf(mx, sz[tid][k]);
      float s = 0.f, ev[KK];
      #pragma unroll
      for (int k = 0; k < KK; k++) { ev[k] = __expf(sz[tid][k] - mx); s += ev[k]; }
      float inv = 1.f / s;
      #pragma unroll
      for (int k = 0; k < KK; k++)
        g_pi[((size_t)((n*HH + h)*LL) + l0 + tid)*KK + k] = ev[k]*inv;
    }
  }

  int lq = tid & 63;            // row (warp-consecutive)
  int f0 = (tid >> 6) * 16;     // 16 consecutive f, uniform per warp
  uint64_t a2[8];
  #pragma unroll
  for (int j = 0; j < 8; j++) a2[j] = 0;
  for (int e = 0; e < EE; e++) {
    uint64_t qp = bcast2(sq[lq][e]);
    const uint64_t* crow = (const uint64_t*)&sc[e][f0];
    #pragma unroll
    for (int v = 0; v < 8; v++)
      a2[v] = ffma2(qp, crow[v], a2[v]);
  }
  size_t htbase = ((size_t)((c*NB + n)*HH + h)*LL + l0 + lq)*EE + f0;
  float4* hdst = (float4*)&g_ht[htbase];
  float ssq = 0.f;
  #pragma unroll
  for (int v = 0; v < 4; v++) {   // short tanh live ranges
    float4 o;
    o.x = tanhf(lo32(a2[v*2+0])); ssq += o.x*o.x;
    o.y = tanhf(hi32(a2[v*2+0])); ssq += o.y*o.y;
    o.z = tanhf(lo32(a2[v*2+1])); ssq += o.z*o.z;
    o.w = tanhf(hi32(a2[v*2+1])); ssq += o.w*o.w;
    hdst[v] = o;
  }
  spart[lq][tid >> 6] = ssq;
  __syncthreads();
  if (tid < 64)
    g_hsq[(size_t)((c*NB + n)*HH + h)*LL + l0 + tid] =
      spart[tid][0] + spart[tid][1] + spart[tid][2] + spart[tid][3];
}

// ---------------------------------------------------------------------------
// Kernel 2: key transpose -> g_keyT[n][h][e][s], and ksq
// ---------------------------------------------------------------------------
__global__ __launch_bounds__(256) void keyprep_kernel(const float* __restrict__ key)
{
  int st = blockIdx.x, h = blockIdx.y, n = blockIdx.z;
  int s0 = st * 64;
  int tid = threadIdx.x;
  __shared__ float sk[64][65];
  for (int idx = tid; idx < 4096; idx += 256) {
    int s = idx >> 6, e = idx & 63;
    sk[s][e] = key[((size_t)((n*SS + s0 + s)*HH + h))*EE + e];
  }
  __syncthreads();
  for (int idx = tid; idx < 4096; idx += 256) {
    int e = idx >> 6, s = idx & 63;
    g_keyT[((size_t)((n*HH + h)*EE) + e)*SS + s0 + s] = sk[s][e];
  }
  if (tid < 64) {
    float a = 0.f;
    #pragma unroll
    for (int e = 0; e < EE; e++) a += sk[tid][e] * sk[tid][e];
    g_ksq[(size_t)(n*HH + h)*SS + s0 + tid] = a;
  }
}

// ---------------------------------------------------------------------------
// Kernel 3: fused logits + softmax + mixture.
// 256-thread CTAs, 4 l-rows x 1024 s per CTA, 3 codes per key pass (2 passes).
// 2 CTAs/SM; cp.async double-buffered key chunks; packed FFMA2 mainloop
// (lanes = s-pairs; kv pairs come free from the 16B smem loads, hv is a
// broadcast LDS.32 duplicated via mov.b64).
// ---------------------------------------------------------------------------
#define TLm 4
#define ECm 8
#define PCC 3      // codes per pass

// smem float offsets
#define SMO_KEY   0          // 2 * 8192 = 16384
#define SMO_MASK  16384      // 4096
#define SMO_HT    20480      // PCC*TLm*EE = 768
#define SMO_KSQ   21248      // 1024
#define SMO_HSQ   22272      // 12 (pad 16)
#define SMO_PI    22288      // 12 (pad 16)
#define SMO_REDM  22304      // 16
#define SMO_REDZ  22320      // 16
#define SMEM_FLOATS 22336
#define SMEM_BYTES (SMEM_FLOATS*4)

__device__ __forceinline__ void cp_async16(uint32_t dst, const float4* src) {
  asm volatile("cp.async.cg.shared.global [%0], [%1], 16;\n" :: "r"(dst), "l"(src));
}
__device__ __forceinline__ void cp_commit() {
  asm volatile("cp.async.commit_group;\n");
}
template<int N> __device__ __forceinline__ void cp_wait() {
  asm volatile("cp.async.wait_group %0;\n" :: "n"(N));
}

__device__ __forceinline__ float kfun(int c, float d, float ns) {
  if (c == 0) return d;                                   // 'L'
  if (c == 1) return -__logf(1.f + ns);                   // 'O' (ns>=0)
  if (c == 2) return -ns;                                 // 'P'
  if (c == 3) { float t = d + 1.f; return t * t; }        // 'Y'
  if (c == 4) return __expf(-0.5f * ns);                  // 'R'
  return __cosf(ns) * __expf(-ns);                        // 'W'
}

__global__ __launch_bounds__(256, 2) void attn_kernel(
    const float* __restrict__ mask, const float* __restrict__ keylen,
    float* __restrict__ out)
{
  extern __shared__ float sm[];
  float* s_key  = sm + SMO_KEY;
  float* s_mask = sm + SMO_MASK;
  float* s_ht   = sm + SMO_HT;
  float* s_ksq  = sm + SMO_KSQ;
  float* s_hsq  = sm + SMO_HSQ;
  float* s_pi   = sm + SMO_PI;
  float* s_redm = sm + SMO_REDM;
  float* s_redz = sm + SMO_REDZ;
  uint32_t skey_u32 = (uint32_t)__cvta_generic_to_shared(s_key);

  int lt = blockIdx.x, h = blockIdx.y, n = blockIdx.z;
  int l0 = lt * TLm;
  int tid  = threadIdx.x;
  int lg   = tid >> 7;        // 0..1 -> rows lg*2 .. lg*2+1
  int si   = tid & 127;       // s = 4*si+r  and  512+4*si+r
  int lane = tid & 31;
  int w4   = si >> 5;

  for (int s = tid; s < SS; s += 256)
    s_ksq[s] = g_ksq[(size_t)(n*HH + h)*SS + s];

  // mask tile + keylen folded (reused by all 6 codes)
  {
    const float4* msrc  = (const float4*)(mask + ((size_t)n*LL + l0)*SS);
    const float4* klsrc = (const float4*)(keylen + (size_t)n*SS);
    float4* mdst = (float4*)s_mask;
    #pragma unroll
    for (int t = 0; t < TLm*SS/4/256; t++) {
      int idx = tid + t*256;
      float4 mv = msrc[idx];
      float4 kv = klsrc[idx & 255];
      mdst[idx] = make_float4(mv.x+kv.x, mv.y+kv.y, mv.z+kv.z, mv.w+kv.w);
    }
  }

  float outacc[2][8];
  #pragma unroll
  for (int i = 0; i < 2; i++)
    #pragma unroll
    for (int j = 0; j < 8; j++) outacc[i][j] = 0.f;

  const float4* ksrc = (const float4*)(g_keyT + (size_t)((n*HH + h)*EE)*SS);

  #pragma unroll 1
  for (int p = 0; p < 2; p++) {
    const int c0 = PCC*p;
    __syncthreads();   // prev pass fully done before rewriting s_ht / s_key

    for (int idx = tid; idx < PCC*TLm*EE; idx += 256) {
      int cc = idx >> 8, off = idx & 255;   // TLm*EE = 256
      s_ht[idx] = g_ht[((size_t)(((c0+cc)*NB + n)*HH + h)*LL + l0)*EE + off];
    }
    if (tid < PCC*TLm) {
      int cc = tid >> 2, l = tid & 3;
      s_hsq[tid] = g_hsq[(size_t)(((c0+cc)*NB + n)*HH + h)*LL + l0 + l];
      s_pi[tid]  = g_pi[((size_t)((n*HH + h)*LL) + l0 + l)*KK + c0 + cc];
    }

    // issue chunk 0
    #pragma unroll
    for (int t = 0; t < 8; t++) {
      int idx = tid + t*256;
      cp_async16(skey_u32 + idx*16, ksrc + idx);
    }
    cp_commit();

    // packed accumulators: [code][row][s-pair], pair = (2 consecutive s)
    uint64_t acc2[PCC][2][4];
    #pragma unroll
    for (int cc = 0; cc < PCC; cc++)
      #pragma unroll
      for (int i = 0; i < 2; i++)
        #pragma unroll
        for (int jp = 0; jp < 4; jp++) acc2[cc][i][jp] = 0;

    #pragma unroll 1
    for (int ec = 0; ec < EE/ECm; ec++) {
      if (ec + 1 < EE/ECm) {
        uint32_t dst = skey_u32 + ((ec+1) & 1) * (ECm*SS*4);
        const float4* src = ksrc + (ec+1)*(ECm*SS/4);
        #pragma unroll
        for (int t = 0; t < 8; t++) {
          int idx = tid + t*256;
          cp_async16(dst + idx*16, src + idx);
        }
        cp_commit();
        cp_wait<1>();
      } else {
        cp_wait<0>();
      }
      __syncthreads();
      const float* kcur = s_key + (ec & 1) * (ECm*SS);
      #pragma unroll
      for (int e = 0; e < ECm; e++) {
        // kv: two 16B loads = 4 packed s-pairs
        ulonglong2 kq0 = *(const ulonglong2*)&kcur[e*SS + 4*si];
        ulonglong2 kq1 = *(const ulonglong2*)&kcur[e*SS + 512 + 4*si];
        uint64_t kvp[4] = {kq0.x, kq0.y, kq1.x, kq1.y};
        #pragma unroll
        for (int cc = 0; cc < PCC; cc++)
          #pragma unroll
          for (int i = 0; i < 2; i++) {
            uint64_t hp = bcast2(s_ht[cc*(TLm*EE) + (lg*2 + i)*EE + ec*ECm + e]);
            #pragma unroll
            for (int jp = 0; jp < 4; jp++)
              acc2[cc][i][jp] = ffma2(hp, kvp[jp], acc2[cc][i][jp]);
          }
      }
      __syncthreads();   // compute done before buffer overwritten next iter
    }

    // --- epilogue: transform + masked softmax + weighted accumulate ---
    float ksqv[8];
    {
      float4 k0 = *(const float4*)&s_ksq[4*si];
      float4 k1 = *(const float4*)&s_ksq[512 + 4*si];
      ksqv[0]=k0.x; ksqv[1]=k0.y; ksqv[2]=k0.z; ksqv[3]=k0.w;
      ksqv[4]=k1.x; ksqv[5]=k1.y; ksqv[6]=k1.z; ksqv[7]=k1.w;
    }
    #pragma unroll
    for (int cc = 0; cc < PCC; cc++) {
      float acc[2][8];
      #pragma unroll
      for (int i = 0; i < 2; i++)
        #pragma unroll
        for (int jp = 0; jp < 4; jp++) {
          acc[i][2*jp+0] = lo32(acc2[cc][i][jp]);
          acc[i][2*jp+1] = hi32(acc2[cc][i][jp]);
        }
      #pragma unroll
      for (int i = 0; i < 2; i++) {
        int l = lg*2 + i;
        float hsqv = s_hsq[cc*TLm + l];
        float4 m0 = *(const float4*)&s_mask[l*SS + 4*si];
        float4 m1 = *(const float4*)&s_mask[l*SS + 512 + 4*si];
        float mkv[8] = {m0.x, m0.y, m0.z, m0.w, m1.x, m1.y, m1.z, m1.w};
        float mm = -3.4e38f;
        #pragma unroll
        for (int j = 0; j < 8; j++) {
          float d  = acc[i][j];
          float ns = hsqv + ksqv[j] - 2.f*d;
          float f  = kfun(c0 + cc, d, ns) + mkv[j];
          acc[i][j] = f;
          mm = fmaxf(mm, f);
        }
        #pragma unroll
        for (int o = 16; o; o >>= 1)
          mm = fmaxf(mm, __shfl_xor_sync(0xffffffffu, mm, o));
        if (lane == 0) s_redm[l*4 + w4] = mm;
      }
      __syncthreads();
      #pragma unroll
      for (int i = 0; i < 2; i++) {
        int l = lg*2 + i;
        float m = fmaxf(fmaxf(s_redm[l*4+0], s_redm[l*4+1]),
                        fmaxf(s_redm[l*4+2], s_redm[l*4+3]));
        float z = 0.f;
        #pragma unroll
        for (int j = 0; j < 8; j++) {
          float ev = __expf(acc[i][j] - m);
          acc[i][j] = ev;
          z += ev;
        }
        #pragma unroll
        for (int o = 16; o; o >>= 1) z += __shfl_xor_sync(0xffffffffu, z, o);
        if (lane == 0) s_redz[l*4 + w4] = z;
      }
      __syncthreads();
      #pragma unroll
      for (int i = 0; i < 2; i++) {
        int l = lg*2 + i;
        float Z = s_redz[l*4+0] + s_redz[l*4+1] + s_redz[l*4+2] + s_redz[l*4+3];
        float coef = s_pi[cc*TLm + l] / Z;
        #pragma unroll
        for (int j = 0; j < 8; j++) outacc[i][j] += coef * acc[i][j];
      }
      // redm rewrite of next cc separated by the redz sync above.
    }
  }

  // coalesced float4 final write from registers
  size_t ob = (size_t)((n*HH + h)*LL + l0 + lg*2)*SS;
  #pragma unroll
  for (int i = 0; i < 2; i++) {
    *(float4*)&out[ob + (size_t)i*SS + 4*si] =
        make_float4(outacc[i][0], outacc[i][1], outacc[i][2], outacc[i][3]);
    *(float4*)&out[ob + (size_t)i*SS + 512 + 4*si] =
        make_float4(outacc[i][4], outacc[i][5], outacc[i][6], outacc[i][7]);
  }
}

// ---------------------------------------------------------------------------
extern "C" void kernel_launch(void* const* d_in, const int* in_sizes, int n_in,
                              void* d_out, int out_size)
{
  const float* q    = (const float*)d_in[0];  // [2,1024,8,64]
  const float* key  = (const float*)d_in[1];  // [2,1024,8,64]
  const float* mask = (const float*)d_in[2];  // [2,1024,1024]
  const float* klen = (const float*)d_in[3];  // [2,1024]
  const float* M    = (const float*)d_in[4];  // [8,64,6]
  const float* C    = (const float*)d_in[5];  // [6,8,64,64]
  float* out = (float*)d_out;                 // [2,8,1024,1024]
  (void)in_sizes; (void)n_in; (void)out_size;

  cudaFuncSetAttribute(attn_kernel,
      cudaFuncAttributeMaxDynamicSharedMemorySize, SMEM_BYTES);

  dim3 gpre(LL/64, HH, NB*KK), bpre(256);
  precompute_kernel<<<gpre, bpre>>>(q, M, C);
  dim3 gkey(LL/64, HH, NB), bkey(256);
  keyprep_kernel<<<gkey, bkey>>>(key);
  dim3 gmain(LL/TLm, HH, NB), bmain(256);
  attn_kernel<<<gmain, bmain, SMEM_BYTES>>>(mask, klen, out);
}